// round 11
// baseline (speedup 1.0000x reference)
#include <cuda_runtime.h>
#include <cuda_bf16.h>

#define BB 16
#define HH 56
#define WWI 56
#define CC 512
#define NHEADS 16
#define DH 32
#define NTOK 49
#define SHIFTV 3
#define NWIN 1024            // B * 64 windows
#define MTOT (NWIN * NTOK)   // 50176
#define NQKV 1536
#define QKV_STRIDE (NWIN * NHEADS * NTOK * DH)
#define XEL (BB * HH * WWI * CC)          // 25690112

// Scratch (device globals; no allocations allowed)
__device__ __nv_bfloat16 g_xb[XEL];               // x in bf16
__device__ __nv_bfloat16 g_wqkv[CC * NQKV];       // qkv_w bf16
__device__ __nv_bfloat16 g_wproj[CC * CC];        // proj_w bf16
__device__ __nv_bfloat16 g_qkvb[3 * QKV_STRIDE];  // [which][win][head][tok][d]
__device__ __nv_bfloat16 g_aob[MTOT * CC];        // attention output bf16

__device__ __forceinline__ unsigned pack_bf16(float lo, float hi) {
    __nv_bfloat162 t = __floats2bfloat162_rn(lo, hi);
    return *(unsigned*)&t;
}
__device__ __forceinline__ unsigned s2u(const void* p) {
    return (unsigned)__cvta_generic_to_shared(p);
}
__device__ __forceinline__ void ldsm4(unsigned* r, unsigned a) {
    asm volatile("ldmatrix.sync.aligned.m8n8.x4.shared.b16 {%0,%1,%2,%3}, [%4];"
        : "=r"(r[0]), "=r"(r[1]), "=r"(r[2]), "=r"(r[3]) : "r"(a));
}
__device__ __forceinline__ void ldsm4t(unsigned* r, unsigned a) {
    asm volatile("ldmatrix.sync.aligned.m8n8.x4.trans.shared.b16 {%0,%1,%2,%3}, [%4];"
        : "=r"(r[0]), "=r"(r[1]), "=r"(r[2]), "=r"(r[3]) : "r"(a));
}
// m16n8k16 bf16 mma (row.col), fp32 accumulate
__device__ __forceinline__ void mma_bf16(float* d, const unsigned* a, const unsigned* b) {
    asm volatile(
        "mma.sync.aligned.m16n8k16.row.col.f32.bf16.bf16.f32 "
        "{%0,%1,%2,%3}, {%4,%5,%6,%7}, {%8,%9}, {%0,%1,%2,%3};\n"
        : "+f"(d[0]), "+f"(d[1]), "+f"(d[2]), "+f"(d[3])
        : "r"(a[0]), "r"(a[1]), "r"(a[2]), "r"(a[3]),
          "r"(b[0]), "r"(b[1]));
}

// fp32 -> bf16, 8 elements per thread
__global__ __launch_bounds__(256) void cvt8(const float* __restrict__ s,
                                            __nv_bfloat16* __restrict__ d, int n8) {
    int i = blockIdx.x * 256 + threadIdx.x;
    if (i >= n8) return;
    const float4* s4 = (const float4*)s;
    float4 a = s4[2 * i], b = s4[2 * i + 1];
    uint4 o;
    o.x = pack_bf16(a.x, a.y); o.y = pack_bf16(a.z, a.w);
    o.z = pack_bf16(b.x, b.y); o.w = pack_bf16(b.z, b.w);
    ((uint4*)d)[i] = o;
}

// ---------------------------------------------------------------------------
// QKV GEMM v4: 256 x 128 x 16 bf16, 256 thr, warps 4x2, warp = 64x64,
// double-buffered smem, ldmatrix fragment loads.
// ---------------------------------------------------------------------------
#define BK 16
#define NCH (CC / BK)   // 32

__global__ __launch_bounds__(256, 1) void qkv_kernel(const float* __restrict__ qkv_b)
{
    __shared__ __nv_bfloat16 Ab[2][256][24];
    __shared__ __nv_bfloat16 Bb[2][BK][136];
    __shared__ int rowBase[256];

    const int tid = threadIdx.x;
    const int lane = tid & 31, wid = tid >> 5;
    const int warp_m = wid & 3, warp_n = wid >> 2;
    const int bm = blockIdx.x * 256, bn = blockIdx.y * 128;

    {
        int m = bm + tid;
        int win = m / NTOK, token = m - win * NTOK;
        int b = win >> 6, widx = win & 63;
        int wh = widx >> 3, ww = widx & 7;
        int th = token / 7, tw = token - th * 7;
        int h = wh * 7 + th + SHIFTV; if (h >= HH)  h -= HH;
        int w = ww * 7 + tw + SHIFTV; if (w >= WWI) w -= WWI;
        rowBase[tid] = ((b * HH + h) * WWI + w) * CC;
    }
    __syncthreads();

    const int rbA = rowBase[tid];                 // A: one full row (16 bf16) per thread
    const int kB = tid >> 4, nB8 = (tid & 15) * 8;

    uint4 a_r0 = *(const uint4*)(g_xb + rbA);
    uint4 a_r1 = *(const uint4*)(g_xb + rbA + 8);
    uint4 b_r  = *(const uint4*)(g_wqkv + kB * NQKV + bn + nB8);

    float acc[4][8][4];
    #pragma unroll
    for (int mi = 0; mi < 4; mi++)
        #pragma unroll
        for (int ni = 0; ni < 8; ni++)
            #pragma unroll
            for (int c = 0; c < 4; c++) acc[mi][ni][c] = 0.f;

    *(uint4*)&Ab[0][tid][0] = a_r0;
    *(uint4*)&Ab[0][tid][8] = a_r1;
    *(uint4*)&Bb[0][kB][nB8] = b_r;
    __syncthreads();

    const int q8 = lane >> 3, lr = lane & 7;
    for (int c = 0; c < NCH; c++) {
        const int buf = c & 1;
        if (c + 1 < NCH) {
            a_r0 = *(const uint4*)(g_xb + rbA + (c + 1) * BK);
            a_r1 = *(const uint4*)(g_xb + rbA + (c + 1) * BK + 8);
            b_r  = *(const uint4*)(g_wqkv + ((c + 1) * BK + kB) * NQKV + bn + nB8);
        }
        unsigned af[4][4], bf[8][2];
        #pragma unroll
        for (int mi = 0; mi < 4; mi++) {
            int row = warp_m * 64 + mi * 16 + (q8 & 1) * 8 + lr;
            ldsm4(af[mi], s2u(&Ab[buf][row][(q8 >> 1) * 8]));
        }
        #pragma unroll
        for (int nj = 0; nj < 4; nj++) {
            unsigned t4[4];
            int kk = (q8 & 1) * 8 + lr;
            int nn = warp_n * 64 + nj * 16 + (q8 >> 1) * 8;
            ldsm4t(t4, s2u(&Bb[buf][kk][nn]));
            bf[2 * nj][0] = t4[0]; bf[2 * nj][1] = t4[1];
            bf[2 * nj + 1][0] = t4[2]; bf[2 * nj + 1][1] = t4[3];
        }
        #pragma unroll
        for (int mi = 0; mi < 4; mi++)
            #pragma unroll
            for (int ni = 0; ni < 8; ni++)
                mma_bf16(acc[mi][ni], af[mi], bf[ni]);
        if (c + 1 < NCH) {
            *(uint4*)&Ab[buf ^ 1][tid][0] = a_r0;
            *(uint4*)&Ab[buf ^ 1][tid][8] = a_r1;
            *(uint4*)&Bb[buf ^ 1][kB][nB8] = b_r;
        }
        __syncthreads();
    }

    const float scale = 0.17677669529663687f;   // 32^-0.5
    #pragma unroll
    for (int mi = 0; mi < 4; mi++) {
        #pragma unroll
        for (int half = 0; half < 2; half++) {
            int m = bm + warp_m * 64 + mi * 16 + (lane >> 2) + half * 8;
            int win = m / NTOK, token = m - win * NTOK;
            #pragma unroll
            for (int ni = 0; ni < 8; ni++) {
                int n = bn + warp_n * 64 + ni * 8 + 2 * (lane & 3);
                float v0 = acc[mi][ni][half * 2 + 0] + qkv_b[n];
                float v1 = acc[mi][ni][half * 2 + 1] + qkv_b[n + 1];
                int which = n >> 9;
                int head = (n >> 5) & 15;
                int dim = n & 31;
                if (which == 0) { v0 *= scale; v1 *= scale; }
                int idx = which * QKV_STRIDE +
                          ((win * NHEADS + head) * NTOK + token) * DH + dim;
                *(__nv_bfloat162*)&g_qkvb[idx] = __floats2bfloat162_rn(v0, v1);
            }
        }
    }
}

// ---------------------------------------------------------------------------
// Fused attention v3: bf16 mma for S=QK^T and O=PV, ldmatrix frags,
// padded 49 -> 64. One block per (window, head), 8 warps (4x2).
// K stored [tok][dim] = n-major B -> non-trans ldsm. V [tok][dim] = k-major
// B -> trans ldsm. P bf16 with zero pad cols; v pad rows zeroed.
// ---------------------------------------------------------------------------
#define NP 64

__global__ __launch_bounds__(256) void attn_kernel(const float* __restrict__ bias_table)
{
    __shared__ __nv_bfloat16 q_s[NP][40];   // 80B stride: 5i mod 8 -> CF ldsm
    __shared__ __nv_bfloat16 k_s[NP][40];
    __shared__ __nv_bfloat16 v_s[NP][40];
    __shared__ float S[NP][68];             // fp32 for softmax
    __shared__ __nv_bfloat16 Pb[NP][72];    // 144B stride: 9i mod 8 -> CF
    __shared__ float biasH[169];
    __shared__ int reg_s[NTOK];

    const int tid = threadIdx.x;
    const int lane = tid & 31, wid = tid >> 5;
    const int warp_m = wid & 3, warp_n = wid >> 2;   // 4 x 2
    const int whid = blockIdx.x;
    const int win = whid >> 4;
    const int head = whid & 15;
    const int base = whid * (NTOK * DH);             // multiple of 8

    const uint4* qp = (const uint4*)(g_qkvb + base);
    const uint4* kp = (const uint4*)(g_qkvb + QKV_STRIDE + base);
    const uint4* vp = (const uint4*)(g_qkvb + 2 * QKV_STRIDE + base);

    if (tid < 196) {                  // 49 toks * 4 uint4 (32 bf16)
        int tok = tid >> 2, part = (tid & 3) * 8;
        *(uint4*)&q_s[tok][part] = qp[tid];
        *(uint4*)&k_s[tok][part] = kp[tid];
        *(uint4*)&v_s[tok][part] = vp[tid];
    } else if (tid < 256) {           // zero v pad rows 49..63 (60 uint4)
        int t = tid - 196;
        int row = NTOK + (t >> 2), part = (t & 3) * 8;
        *(uint4*)&v_s[row][part] = make_uint4(0, 0, 0, 0);
    }
    if (tid < 169) biasH[tid] = bias_table[tid * NHEADS + head];

    const int widx = win & 63;
    const int wwh = widx >> 3, www = widx & 7;
    const bool masked = (wwh == 7) || (www == 7);
    if (tid < NTOK) {
        int th = tid / 7, tw = tid - th * 7;
        int hs = wwh * 7 + th, wsc = www * 7 + tw;
        int rh = hs < 49 ? 0 : (hs < 53 ? 1 : 2);
        int rw = wsc < 49 ? 0 : (wsc < 53 ? 1 : 2);
        reg_s[tid] = rh * 3 + rw;
    }
    __syncthreads();

    const int q8 = lane >> 3, lr = lane & 7;
    const int arl = (q8 & 1) * 8 + lr;          // ldsm row-in-tile
    const int kc8 = (q8 >> 1) * 8;              // ldsm col offset

    // ---- S = q * k^T : warp rows [warp_m*16,+16), cols [warp_n*32,+32)
    float accS[4][4];
    #pragma unroll
    for (int ni = 0; ni < 4; ni++)
        #pragma unroll
        for (int c = 0; c < 4; c++) accS[ni][c] = 0.f;

    {
        unsigned af[2][4];
        #pragma unroll
        for (int kt = 0; kt < 2; kt++)
            ldsm4(af[kt], s2u(&q_s[warp_m * 16 + arl][kt * 16 + kc8]));
        #pragma unroll
        for (int kt = 0; kt < 2; kt++) {
            #pragma unroll
            for (int nj = 0; nj < 2; nj++) {
                unsigned t4[4];   // non-trans from [n][k]: m0=n0-7/k0-7, m1=n8-15/k0-7, m2=n0-7/k8-15, m3=n8-15/k8-15
                ldsm4(t4, s2u(&k_s[warp_n * 32 + nj * 16 + arl][kt * 16 + kc8]));
                unsigned b0[2] = {t4[0], t4[2]};
                unsigned b1[2] = {t4[1], t4[3]};
                mma_bf16(accS[nj * 2 + 0], af[kt], b0);
                mma_bf16(accS[nj * 2 + 1], af[kt], b1);
            }
        }
    }

    // store S with bias + shift mask; padded cols get -1e30
    const int ar = warp_m * 16 + (lane >> 2);
    #pragma unroll
    for (int half = 0; half < 2; half++) {
        int i = ar + half * 8;
        int ri = i / 7, ci = i - ri * 7;
        #pragma unroll
        for (int ni = 0; ni < 4; ni++) {
            #pragma unroll
            for (int cj = 0; cj < 2; cj++) {
                int j = warp_n * 32 + ni * 8 + 2 * (lane & 3) + cj;
                float val = accS[ni][half * 2 + cj];
                if (j >= NTOK) {
                    val = -1e30f;
                } else if (i < NTOK) {
                    int rj = j / 7, cjj = j - rj * 7;
                    val += biasH[(ri - rj + 6) * 13 + (ci - cjj + 6)];
                    if (masked && reg_s[i] != reg_s[j]) val -= 100.f;
                }
                S[i][j] = val;
            }
        }
    }
    __syncthreads();

    // softmax rows; write P bf16 (pad cols -> exp(-1e30)=0 naturally)
    for (int i = wid; i < NTOK; i += 8) {
        float v1 = S[i][lane];
        float v2 = S[i][lane + 32];
        float m = fmaxf(v1, v2);
        #pragma unroll
        for (int o = 16; o > 0; o >>= 1) m = fmaxf(m, __shfl_xor_sync(0xffffffffu, m, o));
        float e1 = __expf(v1 - m);
        float e2 = __expf(v2 - m);
        float sum = e1 + e2;
        #pragma unroll
        for (int o = 16; o > 0; o >>= 1) sum += __shfl_xor_sync(0xffffffffu, sum, o);
        float inv = 1.f / sum;
        Pb[i][lane] = __float2bfloat16(e1 * inv);
        Pb[i][lane + 32] = __float2bfloat16(e2 * inv);
    }
    __syncthreads();

    // ---- O = P * V : warp rows [warp_m*16,+16), dims [warp_n*16,+16)
    float accO[2][4];
    #pragma unroll
    for (int ni = 0; ni < 2; ni++)
        #pragma unroll
        for (int c = 0; c < 4; c++) accO[ni][c] = 0.f;

    #pragma unroll
    for (int kt = 0; kt < 4; kt++) {
        unsigned af[4];
        ldsm4(af, s2u(&Pb[warp_m * 16 + arl][kt * 16 + kc8]));
        unsigned t4[4];   // trans from [k][n]
        ldsm4t(t4, s2u(&v_s[kt * 16 + arl][warp_n * 16 + kc8]));
        unsigned b0[2] = {t4[0], t4[1]};
        unsigned b1[2] = {t4[2], t4[3]};
        mma_bf16(accO[0], af, b0);
        mma_bf16(accO[1], af, b1);
    }

    const int outbase = (win * NTOK) * CC + head * DH;
    #pragma unroll
    for (int half = 0; half < 2; half++) {
        int i = ar + half * 8;
        if (i < NTOK) {
            #pragma unroll
            for (int ni = 0; ni < 2; ni++) {
                int d = warp_n * 16 + ni * 8 + 2 * (lane & 3);
                *(__nv_bfloat162*)&g_aob[outbase + i * CC + d] =
                    __floats2bfloat162_rn(accO[ni][half * 2 + 0], accO[ni][half * 2 + 1]);
            }
        }
    }
}

// ---------------------------------------------------------------------------
// Proj GEMM (bf16, ldsm, double-buffered, 128x128) + residual epilogue
// ---------------------------------------------------------------------------
#define BMp 128

__global__ __launch_bounds__(256, 2) void proj_kernel(
    const float* __restrict__ x,
    const float* __restrict__ proj_b,
    float* __restrict__ out)
{
    __shared__ __nv_bfloat16 Ab[2][BMp][24];
    __shared__ __nv_bfloat16 Bb[2][BK][136];

    const int tid = threadIdx.x;
    const int lane = tid & 31, wid = tid >> 5;
    const int warp_m = wid & 3, warp_n = wid >> 2;
    const int bm = blockIdx.x * BMp, bn = blockIdx.y * 128;

    const int arow = tid >> 1, ahalf = (tid & 1) * 8;
    const int kB = tid >> 4, nB8 = (tid & 15) * 8;

    uint4 a_r = *(const uint4*)(g_aob + (bm + arow) * CC + ahalf);
    uint4 b_r = *(const uint4*)(g_wproj + kB * CC + bn + nB8);

    float acc[2][8][4];
    #pragma unroll
    for (int mi = 0; mi < 2; mi++)
        #pragma unroll
        for (int ni = 0; ni < 8; ni++)
            #pragma unroll
            for (int c = 0; c < 4; c++) acc[mi][ni][c] = 0.f;

    *(uint4*)&Ab[0][arow][ahalf] = a_r;
    *(uint4*)&Bb[0][kB][nB8] = b_r;
    __syncthreads();

    const int q8 = lane >> 3, lr = lane & 7;
    for (int c = 0; c < NCH; c++) {
        const int buf = c & 1;
        if (c + 1 < NCH) {
            a_r = *(const uint4*)(g_aob + (bm + arow) * CC + (c + 1) * BK + ahalf);
            b_r = *(const uint4*)(g_wproj + ((c + 1) * BK + kB) * CC + bn + nB8);
        }
        unsigned af[2][4], bf[8][2];
        #pragma unroll
        for (int mi = 0; mi < 2; mi++) {
            int row = warp_m * 32 + mi * 16 + (q8 & 1) * 8 + lr;
            ldsm4(af[mi], s2u(&Ab[buf][row][(q8 >> 1) * 8]));
        }
        #pragma unroll
        for (int nj = 0; nj < 4; nj++) {
            unsigned t4[4];
            int kk = (q8 & 1) * 8 + lr;
            int nn = warp_n * 64 + nj * 16 + (q8 >> 1) * 8;
            ldsm4t(t4, s2u(&Bb[buf][kk][nn]));
            bf[2 * nj][0] = t4[0]; bf[2 * nj][1] = t4[1];
            bf[2 * nj + 1][0] = t4[2]; bf[2 * nj + 1][1] = t4[3];
        }
        #pragma unroll
        for (int mi = 0; mi < 2; mi++)
            #pragma unroll
            for (int ni = 0; ni < 8; ni++)
                mma_bf16(acc[mi][ni], af[mi], bf[ni]);
        if (c + 1 < NCH) {
            *(uint4*)&Ab[buf ^ 1][arow][ahalf] = a_r;
            *(uint4*)&Bb[buf ^ 1][kB][nB8] = b_r;
        }
        __syncthreads();
    }

    #pragma unroll
    for (int mi = 0; mi < 2; mi++) {
        #pragma unroll
        for (int half = 0; half < 2; half++) {
            int m = bm + warp_m * 32 + mi * 16 + (lane >> 2) + half * 8;
            int win = m / NTOK, token = m - win * NTOK;
            int b = win >> 6, widx = win & 63;
            int wh = widx >> 3, ww = widx & 7;
            int th = token / 7, tw = token - th * 7;
            int h = wh * 7 + th + SHIFTV; if (h >= HH)  h -= HH;
            int w = ww * 7 + tw + SHIFTV; if (w >= WWI) w -= WWI;
            int ob = ((b * HH + h) * WWI + w) * CC;
            #pragma unroll
            for (int ni = 0; ni < 8; ni++) {
                #pragma unroll
                for (int cj = 0; cj < 2; cj++) {
                    int n = bn + warp_n * 64 + ni * 8 + 2 * (lane & 3) + cj;
                    out[ob + n] = x[ob + n] + acc[mi][ni][half * 2 + cj] + proj_b[n];
                }
            }
        }
    }
}

extern "C" void kernel_launch(void* const* d_in, const int* in_sizes, int n_in,
                              void* d_out, int out_size)
{
    const float* x          = (const float*)d_in[0];
    const float* qkv_w      = (const float*)d_in[1];
    const float* qkv_b      = (const float*)d_in[2];
    const float* proj_w     = (const float*)d_in[3];
    const float* proj_b     = (const float*)d_in[4];
    const float* bias_table = (const float*)d_in[5];
    float* out = (float*)d_out;

    __nv_bfloat16 *p_xb, *p_wq, *p_wp;
    cudaGetSymbolAddress((void**)&p_xb, g_xb);
    cudaGetSymbolAddress((void**)&p_wq, g_wqkv);
    cudaGetSymbolAddress((void**)&p_wp, g_wproj);

    cvt8<<<(XEL / 8 + 255) / 256, 256>>>(x, p_xb, XEL / 8);
    cvt8<<<(CC * NQKV / 8 + 255) / 256, 256>>>(qkv_w, p_wq, CC * NQKV / 8);
    cvt8<<<(CC * CC / 8 + 255) / 256, 256>>>(proj_w, p_wp, CC * CC / 8);

    dim3 g1(MTOT / 256, NQKV / 128);   // 196 x 12
    qkv_kernel<<<g1, 256>>>(qkv_b);

    attn_kernel<<<NWIN * NHEADS, 256>>>(bias_table);

    dim3 g3(MTOT / BMp, CC / 128);     // 392 x 4
    proj_kernel<<<g3, 256>>>(x, proj_b, out);
}

// round 12
// speedup vs baseline: 1.1876x; 1.1876x over previous
#include <cuda_runtime.h>
#include <cuda_bf16.h>

#define BB 16
#define HH 56
#define WWI 56
#define CC 512
#define NHEADS 16
#define DH 32
#define NTOK 49
#define SHIFTV 3
#define NWIN 1024            // B * 64 windows
#define MTOT (NWIN * NTOK)   // 50176
#define NQKV 1536
#define QKV_STRIDE (NWIN * NHEADS * NTOK * DH)
#define XEL (BB * HH * WWI * CC)          // 25690112

// Scratch (device globals; no allocations allowed)
__device__ __nv_bfloat16 g_xb[XEL];               // x in bf16
__device__ __nv_bfloat16 g_wqkv[CC * NQKV];       // qkv_w bf16
__device__ __nv_bfloat16 g_wproj[CC * CC];        // proj_w bf16
__device__ __nv_bfloat16 g_qkvb[3 * QKV_STRIDE];  // [which][win][head][tok][d]
__device__ __nv_bfloat16 g_aob[MTOT * CC];        // attention output bf16

__device__ __forceinline__ unsigned pack_bf16(float lo, float hi) {
    __nv_bfloat162 t = __floats2bfloat162_rn(lo, hi);
    return *(unsigned*)&t;
}
__device__ __forceinline__ unsigned s2u(const void* p) {
    return (unsigned)__cvta_generic_to_shared(p);
}
__device__ __forceinline__ void ldsm4(unsigned* r, unsigned a) {
    asm volatile("ldmatrix.sync.aligned.m8n8.x4.shared.b16 {%0,%1,%2,%3}, [%4];"
        : "=r"(r[0]), "=r"(r[1]), "=r"(r[2]), "=r"(r[3]) : "r"(a));
}
__device__ __forceinline__ void ldsm4t(unsigned* r, unsigned a) {
    asm volatile("ldmatrix.sync.aligned.m8n8.x4.trans.shared.b16 {%0,%1,%2,%3}, [%4];"
        : "=r"(r[0]), "=r"(r[1]), "=r"(r[2]), "=r"(r[3]) : "r"(a));
}
// m16n8k16 bf16 mma (row.col), fp32 accumulate
__device__ __forceinline__ void mma_bf16(float* d, const unsigned* a, const unsigned* b) {
    asm volatile(
        "mma.sync.aligned.m16n8k16.row.col.f32.bf16.bf16.f32 "
        "{%0,%1,%2,%3}, {%4,%5,%6,%7}, {%8,%9}, {%0,%1,%2,%3};\n"
        : "+f"(d[0]), "+f"(d[1]), "+f"(d[2]), "+f"(d[3])
        : "r"(a[0]), "r"(a[1]), "r"(a[2]), "r"(a[3]),
          "r"(b[0]), "r"(b[1]));
}

// fp32 -> bf16, 8 elements per thread
__global__ __launch_bounds__(256) void cvt8(const float* __restrict__ s,
                                            __nv_bfloat16* __restrict__ d, int n8) {
    int i = blockIdx.x * 256 + threadIdx.x;
    if (i >= n8) return;
    const float4* s4 = (const float4*)s;
    float4 a = s4[2 * i], b = s4[2 * i + 1];
    uint4 o;
    o.x = pack_bf16(a.x, a.y); o.y = pack_bf16(a.z, a.w);
    o.z = pack_bf16(b.x, b.y); o.w = pack_bf16(b.z, b.w);
    ((uint4*)d)[i] = o;
}

// ---------------------------------------------------------------------------
// QKV GEMM v3 (measured 309us): 128x128x16 bf16, 256 thr, warps 4x2
// (warp 32x64), double-buffered smem, ldmatrix fragment loads.
// ---------------------------------------------------------------------------
#define BM 128
#define BK 16
#define NCH (CC / BK)   // 32

__global__ __launch_bounds__(256, 2) void qkv_kernel(const float* __restrict__ qkv_b)
{
    __shared__ __nv_bfloat16 Ab[2][BM][24];
    __shared__ __nv_bfloat16 Bb[2][BK][136];
    __shared__ int rowBase[BM];

    const int tid = threadIdx.x;
    const int lane = tid & 31, wid = tid >> 5;
    const int warp_m = wid & 3, warp_n = wid >> 2;
    const int bm = blockIdx.x * BM, bn = blockIdx.y * 128;

    if (tid < BM) {
        int m = bm + tid;
        int win = m / NTOK, token = m - win * NTOK;
        int b = win >> 6, widx = win & 63;
        int wh = widx >> 3, ww = widx & 7;
        int th = token / 7, tw = token - th * 7;
        int h = wh * 7 + th + SHIFTV; if (h >= HH)  h -= HH;
        int w = ww * 7 + tw + SHIFTV; if (w >= WWI) w -= WWI;
        rowBase[tid] = ((b * HH + h) * WWI + w) * CC;
    }
    __syncthreads();

    const int arow = tid >> 1, ahalf = (tid & 1) * 8;
    const int rbA = rowBase[arow];
    const int kB = tid >> 4, nB8 = (tid & 15) * 8;

    uint4 a_r = *(const uint4*)(g_xb + rbA + ahalf);
    uint4 b_r = *(const uint4*)(g_wqkv + kB * NQKV + bn + nB8);

    float acc[2][8][4];
    #pragma unroll
    for (int mi = 0; mi < 2; mi++)
        #pragma unroll
        for (int ni = 0; ni < 8; ni++)
            #pragma unroll
            for (int c = 0; c < 4; c++) acc[mi][ni][c] = 0.f;

    *(uint4*)&Ab[0][arow][ahalf] = a_r;
    *(uint4*)&Bb[0][kB][nB8] = b_r;
    __syncthreads();

    const int q8 = lane >> 3, lr = lane & 7;
    for (int c = 0; c < NCH; c++) {
        const int buf = c & 1;
        if (c + 1 < NCH) {
            a_r = *(const uint4*)(g_xb + rbA + (c + 1) * BK + ahalf);
            b_r = *(const uint4*)(g_wqkv + ((c + 1) * BK + kB) * NQKV + bn + nB8);
        }
        unsigned af[2][4], bf[8][2];
        #pragma unroll
        for (int mi = 0; mi < 2; mi++) {
            int row = warp_m * 32 + mi * 16 + (q8 & 1) * 8 + lr;
            ldsm4(af[mi], s2u(&Ab[buf][row][(q8 >> 1) * 8]));
        }
        #pragma unroll
        for (int nj = 0; nj < 4; nj++) {
            unsigned t4[4];
            int kk = (q8 & 1) * 8 + lr;
            int nn = warp_n * 64 + nj * 16 + (q8 >> 1) * 8;
            ldsm4t(t4, s2u(&Bb[buf][kk][nn]));
            bf[2 * nj][0] = t4[0]; bf[2 * nj][1] = t4[1];
            bf[2 * nj + 1][0] = t4[2]; bf[2 * nj + 1][1] = t4[3];
        }
        #pragma unroll
        for (int mi = 0; mi < 2; mi++)
            #pragma unroll
            for (int ni = 0; ni < 8; ni++)
                mma_bf16(acc[mi][ni], af[mi], bf[ni]);
        if (c + 1 < NCH) {
            *(uint4*)&Ab[buf ^ 1][arow][ahalf] = a_r;
            *(uint4*)&Bb[buf ^ 1][kB][nB8] = b_r;
        }
        __syncthreads();
    }

    const float scale = 0.17677669529663687f;   // 32^-0.5
    #pragma unroll
    for (int mi = 0; mi < 2; mi++) {
        #pragma unroll
        for (int half = 0; half < 2; half++) {
            int m = bm + warp_m * 32 + mi * 16 + (lane >> 2) + half * 8;
            int win = m / NTOK, token = m - win * NTOK;
            #pragma unroll
            for (int ni = 0; ni < 8; ni++) {
                int n = bn + warp_n * 64 + ni * 8 + 2 * (lane & 3);
                float v0 = acc[mi][ni][half * 2 + 0] + qkv_b[n];
                float v1 = acc[mi][ni][half * 2 + 1] + qkv_b[n + 1];
                int which = n >> 9;
                int head = (n >> 5) & 15;
                int dim = n & 31;
                if (which == 0) { v0 *= scale; v1 *= scale; }
                int idx = which * QKV_STRIDE +
                          ((win * NHEADS + head) * NTOK + token) * DH + dim;
                *(__nv_bfloat162*)&g_qkvb[idx] = __floats2bfloat162_rn(v0, v1);
            }
        }
    }
}

// ---------------------------------------------------------------------------
// Fused attention v3 (measured ~231us): bf16 mma for S=QK^T and O=PV,
// ldmatrix frags, padded 49 -> 64. One block per (window, head), 8 warps.
// ---------------------------------------------------------------------------
#define NP 64

__global__ __launch_bounds__(256) void attn_kernel(const float* __restrict__ bias_table)
{
    __shared__ __nv_bfloat16 q_s[NP][40];   // 80B stride: 5i mod 8 -> CF ldsm
    __shared__ __nv_bfloat16 k_s[NP][40];
    __shared__ __nv_bfloat16 v_s[NP][40];
    __shared__ float S[NP][68];             // fp32 for softmax
    __shared__ __nv_bfloat16 Pb[NP][72];    // 144B stride: 9i mod 8 -> CF
    __shared__ float biasH[169];
    __shared__ int reg_s[NTOK];

    const int tid = threadIdx.x;
    const int lane = tid & 31, wid = tid >> 5;
    const int warp_m = wid & 3, warp_n = wid >> 2;   // 4 x 2
    const int whid = blockIdx.x;
    const int win = whid >> 4;
    const int head = whid & 15;
    const int base = whid * (NTOK * DH);             // multiple of 8

    const uint4* qp = (const uint4*)(g_qkvb + base);
    const uint4* kp = (const uint4*)(g_qkvb + QKV_STRIDE + base);
    const uint4* vp = (const uint4*)(g_qkvb + 2 * QKV_STRIDE + base);

    if (tid < 196) {                  // 49 toks * 4 uint4 (32 bf16)
        int tok = tid >> 2, part = (tid & 3) * 8;
        *(uint4*)&q_s[tok][part] = qp[tid];
        *(uint4*)&k_s[tok][part] = kp[tid];
        *(uint4*)&v_s[tok][part] = vp[tid];
    } else if (tid < 256) {           // zero v pad rows 49..63 (60 uint4)
        int t = tid - 196;
        int row = NTOK + (t >> 2), part = (t & 3) * 8;
        *(uint4*)&v_s[row][part] = make_uint4(0, 0, 0, 0);
    }
    if (tid < 169) biasH[tid] = bias_table[tid * NHEADS + head];

    const int widx = win & 63;
    const int wwh = widx >> 3, www = widx & 7;
    const bool masked = (wwh == 7) || (www == 7);
    if (tid < NTOK) {
        int th = tid / 7, tw = tid - th * 7;
        int hs = wwh * 7 + th, wsc = www * 7 + tw;
        int rh = hs < 49 ? 0 : (hs < 53 ? 1 : 2);
        int rw = wsc < 49 ? 0 : (wsc < 53 ? 1 : 2);
        reg_s[tid] = rh * 3 + rw;
    }
    __syncthreads();

    const int q8 = lane >> 3, lr = lane & 7;
    const int arl = (q8 & 1) * 8 + lr;          // ldsm row-in-tile
    const int kc8 = (q8 >> 1) * 8;              // ldsm col offset

    // ---- S = q * k^T : warp rows [warp_m*16,+16), cols [warp_n*32,+32)
    float accS[4][4];
    #pragma unroll
    for (int ni = 0; ni < 4; ni++)
        #pragma unroll
        for (int c = 0; c < 4; c++) accS[ni][c] = 0.f;

    {
        unsigned af[2][4];
        #pragma unroll
        for (int kt = 0; kt < 2; kt++)
            ldsm4(af[kt], s2u(&q_s[warp_m * 16 + arl][kt * 16 + kc8]));
        #pragma unroll
        for (int kt = 0; kt < 2; kt++) {
            #pragma unroll
            for (int nj = 0; nj < 2; nj++) {
                unsigned t4[4];   // non-trans from [n][k] layout
                ldsm4(t4, s2u(&k_s[warp_n * 32 + nj * 16 + arl][kt * 16 + kc8]));
                unsigned b0[2] = {t4[0], t4[2]};
                unsigned b1[2] = {t4[1], t4[3]};
                mma_bf16(accS[nj * 2 + 0], af[kt], b0);
                mma_bf16(accS[nj * 2 + 1], af[kt], b1);
            }
        }
    }

    // store S with bias + shift mask; padded cols get -1e30
    const int ar = warp_m * 16 + (lane >> 2);
    #pragma unroll
    for (int half = 0; half < 2; half++) {
        int i = ar + half * 8;
        int ri = i / 7, ci = i - ri * 7;
        #pragma unroll
        for (int ni = 0; ni < 4; ni++) {
            #pragma unroll
            for (int cj = 0; cj < 2; cj++) {
                int j = warp_n * 32 + ni * 8 + 2 * (lane & 3) + cj;
                float val = accS[ni][half * 2 + cj];
                if (j >= NTOK) {
                    val = -1e30f;
                } else if (i < NTOK) {
                    int rj = j / 7, cjj = j - rj * 7;
                    val += biasH[(ri - rj + 6) * 13 + (ci - cjj + 6)];
                    if (masked && reg_s[i] != reg_s[j]) val -= 100.f;
                }
                S[i][j] = val;
            }
        }
    }
    __syncthreads();

    // softmax rows; write P bf16 (pad cols -> exp(-1e30)=0 naturally)
    for (int i = wid; i < NTOK; i += 8) {
        float v1 = S[i][lane];
        float v2 = S[i][lane + 32];
        float m = fmaxf(v1, v2);
        #pragma unroll
        for (int o = 16; o > 0; o >>= 1) m = fmaxf(m, __shfl_xor_sync(0xffffffffu, m, o));
        float e1 = __expf(v1 - m);
        float e2 = __expf(v2 - m);
        float sum = e1 + e2;
        #pragma unroll
        for (int o = 16; o > 0; o >>= 1) sum += __shfl_xor_sync(0xffffffffu, sum, o);
        float inv = 1.f / sum;
        Pb[i][lane] = __float2bfloat16(e1 * inv);
        Pb[i][lane + 32] = __float2bfloat16(e2 * inv);
    }
    __syncthreads();

    // ---- O = P * V : warp rows [warp_m*16,+16), dims [warp_n*16,+16)
    float accO[2][4];
    #pragma unroll
    for (int ni = 0; ni < 2; ni++)
        #pragma unroll
        for (int c = 0; c < 4; c++) accO[ni][c] = 0.f;

    #pragma unroll
    for (int kt = 0; kt < 4; kt++) {
        unsigned af[4];
        ldsm4(af, s2u(&Pb[warp_m * 16 + arl][kt * 16 + kc8]));
        unsigned t4[4];   // trans from [k][n]
        ldsm4t(t4, s2u(&v_s[kt * 16 + arl][warp_n * 16 + kc8]));
        unsigned b0[2] = {t4[0], t4[1]};
        unsigned b1[2] = {t4[2], t4[3]};
        mma_bf16(accO[0], af, b0);
        mma_bf16(accO[1], af, b1);
    }

    const int outbase = (win * NTOK) * CC + head * DH;
    #pragma unroll
    for (int half = 0; half < 2; half++) {
        int i = ar + half * 8;
        if (i < NTOK) {
            #pragma unroll
            for (int ni = 0; ni < 2; ni++) {
                int d = warp_n * 16 + ni * 8 + 2 * (lane & 3);
                *(__nv_bfloat162*)&g_aob[outbase + i * CC + d] =
                    __floats2bfloat162_rn(accO[ni][half * 2 + 0], accO[ni][half * 2 + 1]);
            }
        }
    }
}

// ---------------------------------------------------------------------------
// Proj GEMM (bf16, ldsm, double-buffered, 128x128) + residual epilogue
// ---------------------------------------------------------------------------
__global__ __launch_bounds__(256, 2) void proj_kernel(
    const float* __restrict__ x,
    const float* __restrict__ proj_b,
    float* __restrict__ out)
{
    __shared__ __nv_bfloat16 Ab[2][BM][24];
    __shared__ __nv_bfloat16 Bb[2][BK][136];

    const int tid = threadIdx.x;
    const int lane = tid & 31, wid = tid >> 5;
    const int warp_m = wid & 3, warp_n = wid >> 2;
    const int bm = blockIdx.x * BM, bn = blockIdx.y * 128;

    const int arow = tid >> 1, ahalf = (tid & 1) * 8;
    const int kB = tid >> 4, nB8 = (tid & 15) * 8;

    uint4 a_r = *(const uint4*)(g_aob + (bm + arow) * CC + ahalf);
    uint4 b_r = *(const uint4*)(g_wproj + kB * CC + bn + nB8);

    float acc[2][8][4];
    #pragma unroll
    for (int mi = 0; mi < 2; mi++)
        #pragma unroll
        for (int ni = 0; ni < 8; ni++)
            #pragma unroll
            for (int c = 0; c < 4; c++) acc[mi][ni][c] = 0.f;

    *(uint4*)&Ab[0][arow][ahalf] = a_r;
    *(uint4*)&Bb[0][kB][nB8] = b_r;
    __syncthreads();

    const int q8 = lane >> 3, lr = lane & 7;
    for (int c = 0; c < NCH; c++) {
        const int buf = c & 1;
        if (c + 1 < NCH) {
            a_r = *(const uint4*)(g_aob + (bm + arow) * CC + (c + 1) * BK + ahalf);
            b_r = *(const uint4*)(g_wproj + ((c + 1) * BK + kB) * CC + bn + nB8);
        }
        unsigned af[2][4], bf[8][2];
        #pragma unroll
        for (int mi = 0; mi < 2; mi++) {
            int row = warp_m * 32 + mi * 16 + (q8 & 1) * 8 + lr;
            ldsm4(af[mi], s2u(&Ab[buf][row][(q8 >> 1) * 8]));
        }
        #pragma unroll
        for (int nj = 0; nj < 4; nj++) {
            unsigned t4[4];
            int kk = (q8 & 1) * 8 + lr;
            int nn = warp_n * 64 + nj * 16 + (q8 >> 1) * 8;
            ldsm4t(t4, s2u(&Bb[buf][kk][nn]));
            bf[2 * nj][0] = t4[0]; bf[2 * nj][1] = t4[1];
            bf[2 * nj + 1][0] = t4[2]; bf[2 * nj + 1][1] = t4[3];
        }
        #pragma unroll
        for (int mi = 0; mi < 2; mi++)
            #pragma unroll
            for (int ni = 0; ni < 8; ni++)
                mma_bf16(acc[mi][ni], af[mi], bf[ni]);
        if (c + 1 < NCH) {
            *(uint4*)&Ab[buf ^ 1][arow][ahalf] = a_r;
            *(uint4*)&Bb[buf ^ 1][kB][nB8] = b_r;
        }
        __syncthreads();
    }

    #pragma unroll
    for (int mi = 0; mi < 2; mi++) {
        #pragma unroll
        for (int half = 0; half < 2; half++) {
            int m = bm + warp_m * 32 + mi * 16 + (lane >> 2) + half * 8;
            int win = m / NTOK, token = m - win * NTOK;
            int b = win >> 6, widx = win & 63;
            int wh = widx >> 3, ww = widx & 7;
            int th = token / 7, tw = token - th * 7;
            int h = wh * 7 + th + SHIFTV; if (h >= HH)  h -= HH;
            int w = ww * 7 + tw + SHIFTV; if (w >= WWI) w -= WWI;
            int ob = ((b * HH + h) * WWI + w) * CC;
            #pragma unroll
            for (int ni = 0; ni < 8; ni++) {
                #pragma unroll
                for (int cj = 0; cj < 2; cj++) {
                    int n = bn + warp_n * 64 + ni * 8 + 2 * (lane & 3) + cj;
                    out[ob + n] = x[ob + n] + acc[mi][ni][half * 2 + cj] + proj_b[n];
                }
            }
        }
    }
}

extern "C" void kernel_launch(void* const* d_in, const int* in_sizes, int n_in,
                              void* d_out, int out_size)
{
    const float* x          = (const float*)d_in[0];
    const float* qkv_w      = (const float*)d_in[1];
    const float* qkv_b      = (const float*)d_in[2];
    const float* proj_w     = (const float*)d_in[3];
    const float* proj_b     = (const float*)d_in[4];
    const float* bias_table = (const float*)d_in[5];
    float* out = (float*)d_out;

    __nv_bfloat16 *p_xb, *p_wq, *p_wp;
    cudaGetSymbolAddress((void**)&p_xb, g_xb);
    cudaGetSymbolAddress((void**)&p_wq, g_wqkv);
    cudaGetSymbolAddress((void**)&p_wp, g_wproj);

    cvt8<<<(XEL / 8 + 255) / 256, 256>>>(x, p_xb, XEL / 8);
    cvt8<<<(CC * NQKV / 8 + 255) / 256, 256>>>(qkv_w, p_wq, CC * NQKV / 8);
    cvt8<<<(CC * CC / 8 + 255) / 256, 256>>>(proj_w, p_wp, CC * CC / 8);

    dim3 g1(MTOT / BM, NQKV / 128);    // 392 x 12
    qkv_kernel<<<g1, 256>>>(qkv_b);

    attn_kernel<<<NWIN * NHEADS, 256>>>(bias_table);

    dim3 g3(MTOT / BM, CC / 128);      // 392 x 4
    proj_kernel<<<g3, 256>>>(x, proj_b, out);
}

// round 16
// speedup vs baseline: 1.2771x; 1.0753x over previous
#include <cuda_runtime.h>
#include <cuda_bf16.h>

#define BB 16
#define HH 56
#define WWI 56
#define CC 512
#define NHEADS 16
#define DH 32
#define NTOK 49
#define SHIFTV 3
#define NWIN 1024            // B * 64 windows
#define MTOT (NWIN * NTOK)   // 50176
#define NQKV 1536
#define QKV_STRIDE (NWIN * NHEADS * NTOK * DH)
#define XEL (BB * HH * WWI * CC)          // 25690112

// Scratch (device globals; no allocations allowed)
__device__ __nv_bfloat16 g_xb[XEL];               // x in bf16
__device__ __nv_bfloat16 g_wqkv[CC * NQKV];       // qkv_w bf16
__device__ __nv_bfloat16 g_wproj[CC * CC];        // proj_w bf16
__device__ __nv_bfloat16 g_qkvb[3 * QKV_STRIDE];  // [which][win][head][tok][d]
__device__ __nv_bfloat16 g_aob[MTOT * CC];        // attention output bf16

__device__ __forceinline__ unsigned pack_bf16(float lo, float hi) {
    __nv_bfloat162 t = __floats2bfloat162_rn(lo, hi);
    return *(unsigned*)&t;
}
__device__ __forceinline__ unsigned s2u(const void* p) {
    return (unsigned)__cvta_generic_to_shared(p);
}
__device__ __forceinline__ void ldsm4(unsigned* r, unsigned a) {
    asm volatile("ldmatrix.sync.aligned.m8n8.x4.shared.b16 {%0,%1,%2,%3}, [%4];"
        : "=r"(r[0]), "=r"(r[1]), "=r"(r[2]), "=r"(r[3]) : "r"(a));
}
__device__ __forceinline__ void ldsm4t(unsigned* r, unsigned a) {
    asm volatile("ldmatrix.sync.aligned.m8n8.x4.trans.shared.b16 {%0,%1,%2,%3}, [%4];"
        : "=r"(r[0]), "=r"(r[1]), "=r"(r[2]), "=r"(r[3]) : "r"(a));
}
// m16n8k16 bf16 mma (row.col), fp32 accumulate
__device__ __forceinline__ void mma_bf16(float* d, const unsigned* a, const unsigned* b) {
    asm volatile(
        "mma.sync.aligned.m16n8k16.row.col.f32.bf16.bf16.f32 "
        "{%0,%1,%2,%3}, {%4,%5,%6,%7}, {%8,%9}, {%0,%1,%2,%3};\n"
        : "+f"(d[0]), "+f"(d[1]), "+f"(d[2]), "+f"(d[3])
        : "r"(a[0]), "r"(a[1]), "r"(a[2]), "r"(a[3]),
          "r"(b[0]), "r"(b[1]));
}

// fp32 -> bf16, 8 elements per thread
__global__ __launch_bounds__(256) void cvt8(const float* __restrict__ s,
                                            __nv_bfloat16* __restrict__ d, int n8) {
    int i = blockIdx.x * 256 + threadIdx.x;
    if (i >= n8) return;
    const float4* s4 = (const float4*)s;
    float4 a = s4[2 * i], b = s4[2 * i + 1];
    uint4 o;
    o.x = pack_bf16(a.x, a.y); o.y = pack_bf16(a.z, a.w);
    o.z = pack_bf16(b.x, b.y); o.w = pack_bf16(b.z, b.w);
    ((uint4*)d)[i] = o;
}

// ---------------------------------------------------------------------------
// QKV GEMM v3 (measured 309us): 128x128x16 bf16, 256 thr, warps 4x2
// (warp 32x64), double-buffered smem, ldmatrix fragment loads.
// ---------------------------------------------------------------------------
#define BM 128
#define BK 16
#define NCH (CC / BK)   // 32

__global__ __launch_bounds__(256, 2) void qkv_kernel(const float* __restrict__ qkv_b)
{
    __shared__ __nv_bfloat16 Ab[2][BM][24];
    __shared__ __nv_bfloat16 Bb[2][BK][136];
    __shared__ int rowBase[BM];

    const int tid = threadIdx.x;
    const int lane = tid & 31, wid = tid >> 5;
    const int warp_m = wid & 3, warp_n = wid >> 2;
    const int bm = blockIdx.x * BM, bn = blockIdx.y * 128;

    if (tid < BM) {
        int m = bm + tid;
        int win = m / NTOK, token = m - win * NTOK;
        int b = win >> 6, widx = win & 63;
        int wh = widx >> 3, ww = widx & 7;
        int th = token / 7, tw = token - th * 7;
        int h = wh * 7 + th + SHIFTV; if (h >= HH)  h -= HH;
        int w = ww * 7 + tw + SHIFTV; if (w >= WWI) w -= WWI;
        rowBase[tid] = ((b * HH + h) * WWI + w) * CC;
    }
    __syncthreads();

    const int arow = tid >> 1, ahalf = (tid & 1) * 8;
    const int rbA = rowBase[arow];
    const int kB = tid >> 4, nB8 = (tid & 15) * 8;

    uint4 a_r = *(const uint4*)(g_xb + rbA + ahalf);
    uint4 b_r = *(const uint4*)(g_wqkv + kB * NQKV + bn + nB8);

    float acc[2][8][4];
    #pragma unroll
    for (int mi = 0; mi < 2; mi++)
        #pragma unroll
        for (int ni = 0; ni < 8; ni++)
            #pragma unroll
            for (int c = 0; c < 4; c++) acc[mi][ni][c] = 0.f;

    *(uint4*)&Ab[0][arow][ahalf] = a_r;
    *(uint4*)&Bb[0][kB][nB8] = b_r;
    __syncthreads();

    const int q8 = lane >> 3, lr = lane & 7;
    for (int c = 0; c < NCH; c++) {
        const int buf = c & 1;
        if (c + 1 < NCH) {
            a_r = *(const uint4*)(g_xb + rbA + (c + 1) * BK + ahalf);
            b_r = *(const uint4*)(g_wqkv + ((c + 1) * BK + kB) * NQKV + bn + nB8);
        }
        unsigned af[2][4], bf[8][2];
        #pragma unroll
        for (int mi = 0; mi < 2; mi++) {
            int row = warp_m * 32 + mi * 16 + (q8 & 1) * 8 + lr;
            ldsm4(af[mi], s2u(&Ab[buf][row][(q8 >> 1) * 8]));
        }
        #pragma unroll
        for (int nj = 0; nj < 4; nj++) {
            unsigned t4[4];
            int kk = (q8 & 1) * 8 + lr;
            int nn = warp_n * 64 + nj * 16 + (q8 >> 1) * 8;
            ldsm4t(t4, s2u(&Bb[buf][kk][nn]));
            bf[2 * nj][0] = t4[0]; bf[2 * nj][1] = t4[1];
            bf[2 * nj + 1][0] = t4[2]; bf[2 * nj + 1][1] = t4[3];
        }
        #pragma unroll
        for (int mi = 0; mi < 2; mi++)
            #pragma unroll
            for (int ni = 0; ni < 8; ni++)
                mma_bf16(acc[mi][ni], af[mi], bf[ni]);
        if (c + 1 < NCH) {
            *(uint4*)&Ab[buf ^ 1][arow][ahalf] = a_r;
            *(uint4*)&Bb[buf ^ 1][kB][nB8] = b_r;
        }
        __syncthreads();
    }

    const float scale = 0.17677669529663687f;   // 32^-0.5
    #pragma unroll
    for (int mi = 0; mi < 2; mi++) {
        #pragma unroll
        for (int half = 0; half < 2; half++) {
            int m = bm + warp_m * 32 + mi * 16 + (lane >> 2) + half * 8;
            int win = m / NTOK, token = m - win * NTOK;
            #pragma unroll
            for (int ni = 0; ni < 8; ni++) {
                int n = bn + warp_n * 64 + ni * 8 + 2 * (lane & 3);
                float v0 = acc[mi][ni][half * 2 + 0] + qkv_b[n];
                float v1 = acc[mi][ni][half * 2 + 1] + qkv_b[n + 1];
                int which = n >> 9;
                int head = (n >> 5) & 15;
                int dim = n & 31;
                if (which == 0) { v0 *= scale; v1 *= scale; }
                int idx = which * QKV_STRIDE +
                          ((win * NHEADS + head) * NTOK + token) * DH + dim;
                *(__nv_bfloat162*)&g_qkvb[idx] = __floats2bfloat162_rn(v0, v1);
            }
        }
    }
}

// ---------------------------------------------------------------------------
// Fused attention v4.1: warp-owns-rows layout. 2 heads per block, 8 warps
// (4 per head, 16 rows x all 64 cols each). Softmax fully in registers
// (shfl over the 4 lanes sharing a row); P feeds PV mma directly from
// registers. Fix vs v4: bias table load is a strided loop (338 > 256).
// ---------------------------------------------------------------------------
#define NP 64

__global__ __launch_bounds__(256) void attn_kernel(const float* __restrict__ bias_table)
{
    __shared__ __nv_bfloat16 q_s[2][NP][40];   // stride 40 (80B): CF ldsm
    __shared__ __nv_bfloat16 k_s[2][NP][40];
    __shared__ __nv_bfloat16 v_s[2][NP][40];
    __shared__ float biasH[2][169];
    __shared__ int reg_s[NTOK];

    const int tid = threadIdx.x;
    const int lane = tid & 31, wid = tid >> 5;
    const int h = wid >> 2;            // head-in-pair (0/1)
    const int warp_m = wid & 3;        // 16-row slice
    const int bid = blockIdx.x;
    const int win = bid >> 3;
    const int hp = bid & 7;            // head pair

    // load q/k/v for both heads (2*3*196 uint4)
    for (int idx = tid; idx < 1176; idx += 256) {
        int hh = idx / 588;
        int r = idx - hh * 588;
        int t = r / 196;
        int e = r - t * 196;
        int tok = e >> 2, part = (e & 3) * 8;
        const uint4* src = (const uint4*)(g_qkvb + t * QKV_STRIDE +
                           (win * NHEADS + hp * 2 + hh) * (NTOK * DH));
        uint4 val = src[e];
        if (t == 0)      *(uint4*)&q_s[hh][tok][part] = val;
        else if (t == 1) *(uint4*)&k_s[hh][tok][part] = val;
        else             *(uint4*)&v_s[hh][tok][part] = val;
    }
    // zero pad rows 49..63 of k and v (2 heads * 2 tensors * 15 rows * 4 uint4)
    for (int idx = tid; idx < 240; idx += 256) {
        int hh = idx / 120;
        int r = idx - hh * 120;
        int t = r / 60;
        int e = r - t * 60;
        int row = NTOK + (e >> 2), part = (e & 3) * 8;
        if (t == 0) *(uint4*)&k_s[hh][row][part] = make_uint4(0, 0, 0, 0);
        else        *(uint4*)&v_s[hh][row][part] = make_uint4(0, 0, 0, 0);
    }
    for (int idx = tid; idx < 338; idx += 256) {      // FIX: strided (338 > 256)
        int hh = idx / 169, i = idx - hh * 169;
        biasH[hh][i] = bias_table[i * NHEADS + hp * 2 + hh];
    }
    const int widx = win & 63;
    const int wwh = widx >> 3, www = widx & 7;
    const bool masked = (wwh == 7) || (www == 7);
    if (tid < NTOK) {
        int th = tid / 7, tw = tid - th * 7;
        int hs = wwh * 7 + th, wsc = www * 7 + tw;
        int rh = hs < 49 ? 0 : (hs < 53 ? 1 : 2);
        int rw = wsc < 49 ? 0 : (wsc < 53 ? 1 : 2);
        reg_s[tid] = rh * 3 + rw;
    }
    __syncthreads();

    const int q8 = lane >> 3, lr = lane & 7;
    const int arl = (q8 & 1) * 8 + lr;
    const int kc8 = (q8 >> 1) * 8;

    // ---- S = q * k^T : warp rows [warp_m*16,+16) x all 64 cols
    float accS[8][4];
    #pragma unroll
    for (int ni = 0; ni < 8; ni++)
        #pragma unroll
        for (int c = 0; c < 4; c++) accS[ni][c] = 0.f;

    {
        unsigned af[2][4];
        #pragma unroll
        for (int kt = 0; kt < 2; kt++)
            ldsm4(af[kt], s2u(&q_s[h][warp_m * 16 + arl][kt * 16 + kc8]));
        #pragma unroll
        for (int kt = 0; kt < 2; kt++) {
            #pragma unroll
            for (int nj = 0; nj < 4; nj++) {
                unsigned t4[4];
                ldsm4(t4, s2u(&k_s[h][nj * 16 + arl][kt * 16 + kc8]));
                unsigned b0[2] = {t4[0], t4[2]};
                unsigned b1[2] = {t4[1], t4[3]};
                mma_bf16(accS[nj * 2 + 0], af[kt], b0);
                mma_bf16(accS[nj * 2 + 1], af[kt], b1);
            }
        }
    }

    // ---- bias + mask in registers
    const int jbase = 2 * (lane & 3);
    const int i0 = warp_m * 16 + (lane >> 2), i1 = i0 + 8;
    const int ri0 = i0 / 7, ci0 = i0 - ri0 * 7;
    const int ri1 = i1 / 7, ci1 = i1 - ri1 * 7;
    const int rs0 = (i0 < NTOK) ? reg_s[i0] : 0;
    const int rs1 = (i1 < NTOK) ? reg_s[i1] : 0;
    #pragma unroll
    for (int ni = 0; ni < 8; ni++) {
        #pragma unroll
        for (int cj = 0; cj < 2; cj++) {
            int j = ni * 8 + jbase + cj;
            bool jv = (j < NTOK);
            int rj = j / 7, cjj = j - rj * 7;
            int rsj = jv ? reg_s[j] : 0;
            float v = accS[ni][cj];
            if (!jv) v = -1e30f;
            else if (i0 < NTOK) {
                v += biasH[h][(ri0 - rj + 6) * 13 + (ci0 - cjj + 6)];
                if (masked && rs0 != rsj) v -= 100.f;
            }
            accS[ni][cj] = v;
            float w = accS[ni][cj + 2];
            if (!jv) w = -1e30f;
            else if (i1 < NTOK) {
                w += biasH[h][(ri1 - rj + 6) * 13 + (ci1 - cjj + 6)];
                if (masked && rs1 != rsj) w -= 100.f;
            }
            accS[ni][cj + 2] = w;
        }
    }

    // ---- softmax in registers (rows i0, i1), shfl over 4 lanes sharing row
    float m0 = -1e30f, m1 = -1e30f;
    #pragma unroll
    for (int ni = 0; ni < 8; ni++) {
        m0 = fmaxf(m0, fmaxf(accS[ni][0], accS[ni][1]));
        m1 = fmaxf(m1, fmaxf(accS[ni][2], accS[ni][3]));
    }
    m0 = fmaxf(m0, __shfl_xor_sync(0xffffffffu, m0, 1));
    m0 = fmaxf(m0, __shfl_xor_sync(0xffffffffu, m0, 2));
    m1 = fmaxf(m1, __shfl_xor_sync(0xffffffffu, m1, 1));
    m1 = fmaxf(m1, __shfl_xor_sync(0xffffffffu, m1, 2));
    float s0 = 0.f, s1 = 0.f;
    #pragma unroll
    for (int ni = 0; ni < 8; ni++) {
        accS[ni][0] = __expf(accS[ni][0] - m0); s0 += accS[ni][0];
        accS[ni][1] = __expf(accS[ni][1] - m0); s0 += accS[ni][1];
        accS[ni][2] = __expf(accS[ni][2] - m1); s1 += accS[ni][2];
        accS[ni][3] = __expf(accS[ni][3] - m1); s1 += accS[ni][3];
    }
    s0 += __shfl_xor_sync(0xffffffffu, s0, 1);
    s0 += __shfl_xor_sync(0xffffffffu, s0, 2);
    s1 += __shfl_xor_sync(0xffffffffu, s1, 1);
    s1 += __shfl_xor_sync(0xffffffffu, s1, 2);
    const float inv0 = 1.f / s0, inv1 = 1.f / s1;

    // ---- pack P directly into A-fragments (no smem round trip)
    unsigned pf[4][4];
    #pragma unroll
    for (int kt = 0; kt < 4; kt++) {
        pf[kt][0] = pack_bf16(accS[2 * kt][0] * inv0, accS[2 * kt][1] * inv0);
        pf[kt][1] = pack_bf16(accS[2 * kt][2] * inv1, accS[2 * kt][3] * inv1);
        pf[kt][2] = pack_bf16(accS[2 * kt + 1][0] * inv0, accS[2 * kt + 1][1] * inv0);
        pf[kt][3] = pack_bf16(accS[2 * kt + 1][2] * inv1, accS[2 * kt + 1][3] * inv1);
    }

    // ---- O = P * V : warp rows x all 32 dims
    float accO[4][4];
    #pragma unroll
    for (int dn = 0; dn < 4; dn++)
        #pragma unroll
        for (int c = 0; c < 4; c++) accO[dn][c] = 0.f;

    #pragma unroll
    for (int kt = 0; kt < 4; kt++) {
        #pragma unroll
        for (int dn = 0; dn < 2; dn++) {
            unsigned t4[4];
            ldsm4t(t4, s2u(&v_s[h][kt * 16 + arl][dn * 16 + kc8]));
            unsigned b0[2] = {t4[0], t4[1]};
            unsigned b1[2] = {t4[2], t4[3]};
            mma_bf16(accO[dn * 2 + 0], pf[kt], b0);
            mma_bf16(accO[dn * 2 + 1], pf[kt], b1);
        }
    }

    // ---- store
    const int outbase = (win * NTOK) * CC + (hp * 2 + h) * DH;
    #pragma unroll
    for (int half = 0; half < 2; half++) {
        int i = i0 + half * 8;
        if (i < NTOK) {
            #pragma unroll
            for (int dn = 0; dn < 4; dn++) {
                int d = dn * 8 + jbase;
                *(__nv_bfloat162*)&g_aob[outbase + i * CC + d] =
                    __floats2bfloat162_rn(accO[dn][half * 2 + 0], accO[dn][half * 2 + 1]);
            }
        }
    }
}

// ---------------------------------------------------------------------------
// Proj GEMM (bf16, ldsm, double-buffered, 128x128) + residual epilogue
// ---------------------------------------------------------------------------
__global__ __launch_bounds__(256, 2) void proj_kernel(
    const float* __restrict__ x,
    const float* __restrict__ proj_b,
    float* __restrict__ out)
{
    __shared__ __nv_bfloat16 Ab[2][BM][24];
    __shared__ __nv_bfloat16 Bb[2][BK][136];

    const int tid = threadIdx.x;
    const int lane = tid & 31, wid = tid >> 5;
    const int warp_m = wid & 3, warp_n = wid >> 2;
    const int bm = blockIdx.x * BM, bn = blockIdx.y * 128;

    const int arow = tid >> 1, ahalf = (tid & 1) * 8;
    const int kB = tid >> 4, nB8 = (tid & 15) * 8;

    uint4 a_r = *(const uint4*)(g_aob + (bm + arow) * CC + ahalf);
    uint4 b_r = *(const uint4*)(g_wproj + kB * CC + bn + nB8);

    float acc[2][8][4];
    #pragma unroll
    for (int mi = 0; mi < 2; mi++)
        #pragma unroll
        for (int ni = 0; ni < 8; ni++)
            #pragma unroll
            for (int c = 0; c < 4; c++) acc[mi][ni][c] = 0.f;

    *(uint4*)&Ab[0][arow][ahalf] = a_r;
    *(uint4*)&Bb[0][kB][nB8] = b_r;
    __syncthreads();

    const int q8 = lane >> 3, lr = lane & 7;
    for (int c = 0; c < NCH; c++) {
        const int buf = c & 1;
        if (c + 1 < NCH) {
            a_r = *(const uint4*)(g_aob + (bm + arow) * CC + (c + 1) * BK + ahalf);
            b_r = *(const uint4*)(g_wproj + ((c + 1) * BK + kB) * CC + bn + nB8);
        }
        unsigned af[2][4], bf[8][2];
        #pragma unroll
        for (int mi = 0; mi < 2; mi++) {
            int row = warp_m * 32 + mi * 16 + (q8 & 1) * 8 + lr;
            ldsm4(af[mi], s2u(&Ab[buf][row][(q8 >> 1) * 8]));
        }
        #pragma unroll
        for (int nj = 0; nj < 4; nj++) {
            unsigned t4[4];
            int kk = (q8 & 1) * 8 + lr;
            int nn = warp_n * 64 + nj * 16 + (q8 >> 1) * 8;
            ldsm4t(t4, s2u(&Bb[buf][kk][nn]));
            bf[2 * nj][0] = t4[0]; bf[2 * nj][1] = t4[1];
            bf[2 * nj + 1][0] = t4[2]; bf[2 * nj + 1][1] = t4[3];
        }
        #pragma unroll
        for (int mi = 0; mi < 2; mi++)
            #pragma unroll
            for (int ni = 0; ni < 8; ni++)
                mma_bf16(acc[mi][ni], af[mi], bf[ni]);
        if (c + 1 < NCH) {
            *(uint4*)&Ab[buf ^ 1][arow][ahalf] = a_r;
            *(uint4*)&Bb[buf ^ 1][kB][nB8] = b_r;
        }
        __syncthreads();
    }

    #pragma unroll
    for (int mi = 0; mi < 2; mi++) {
        #pragma unroll
        for (int half = 0; half < 2; half++) {
            int m = bm + warp_m * 32 + mi * 16 + (lane >> 2) + half * 8;
            int win = m / NTOK, token = m - win * NTOK;
            int b = win >> 6, widx = win & 63;
            int wh = widx >> 3, ww = widx & 7;
            int th = token / 7, tw = token - th * 7;
            int h = wh * 7 + th + SHIFTV; if (h >= HH)  h -= HH;
            int w = ww * 7 + tw + SHIFTV; if (w >= WWI) w -= WWI;
            int ob = ((b * HH + h) * WWI + w) * CC;
            #pragma unroll
            for (int ni = 0; ni < 8; ni++) {
                #pragma unroll
                for (int cj = 0; cj < 2; cj++) {
                    int n = bn + warp_n * 64 + ni * 8 + 2 * (lane & 3) + cj;
                    out[ob + n] = x[ob + n] + acc[mi][ni][half * 2 + cj] + proj_b[n];
                }
            }
        }
    }
}

extern "C" void kernel_launch(void* const* d_in, const int* in_sizes, int n_in,
                              void* d_out, int out_size)
{
    const float* x          = (const float*)d_in[0];
    const float* qkv_w      = (const float*)d_in[1];
    const float* qkv_b      = (const float*)d_in[2];
    const float* proj_w     = (const float*)d_in[3];
    const float* proj_b     = (const float*)d_in[4];
    const float* bias_table = (const float*)d_in[5];
    float* out = (float*)d_out;

    __nv_bfloat16 *p_xb, *p_wq, *p_wp;
    cudaGetSymbolAddress((void**)&p_xb, g_xb);
    cudaGetSymbolAddress((void**)&p_wq, g_wqkv);
    cudaGetSymbolAddress((void**)&p_wp, g_wproj);

    cvt8<<<(XEL / 8 + 255) / 256, 256>>>(x, p_xb, XEL / 8);
    cvt8<<<(CC * NQKV / 8 + 255) / 256, 256>>>(qkv_w, p_wq, CC * NQKV / 8);
    cvt8<<<(CC * CC / 8 + 255) / 256, 256>>>(proj_w, p_wp, CC * CC / 8);

    dim3 g1(MTOT / BM, NQKV / 128);    // 392 x 12
    qkv_kernel<<<g1, 256>>>(qkv_b);

    attn_kernel<<<NWIN * NHEADS / 2, 256>>>(bias_table);

    dim3 g3(MTOT / BM, CC / 128);      // 392 x 4
    proj_kernel<<<g3, 256>>>(x, proj_b, out);
}